// round 2
// baseline (speedup 1.0000x reference)
#include <cuda_runtime.h>
#include <math.h>

#define DX 512
#define DU 256
#define DOUT 256
#define DK 768
#define NB 16
#define SEQL 4096
#define CT 64          // chunk length
#define CW 64          // warmup length
#define OUT_ELEMS (NB*SEQL*DOUT)          /* 16777216 */
#define ST_ELEMS  ((size_t)NB*(SEQL+1)*DX) /* 33562624 */

// ---------------- device scratch (static; no runtime allocation) ----------------
__device__ float g_M0[DK*DK];
__device__ float g_M1[DK*DK];
__device__ float g_Xa[DX*DX];
__device__ float g_Xb[DX*DX];
__device__ float g_P[DX*DX];
__device__ float g_T1[DX*DX];
__device__ float g_Amat[DX*DX];
__device__ float g_Apack[DX*DX];
__device__ float g_Bm[DX*DU];
__device__ float g_E[DOUT*DK];
__device__ float g_Bu[(size_t)NB*SEQL*DX];
__device__ float g_states_fallback[(size_t)NB*(SEQL+1)*DX];
__device__ float g_scale;
__device__ float g_kscale;
__device__ double g_logacc;

// ---------------- small kernels ----------------
__global__ void init_kernel() {
    int idx = blockIdx.x * blockDim.x + threadIdx.x;
    if (idx == 0) g_logacc = 0.0;
    if (idx < DX*DX) {
        int i = idx / DX, j = idx - i*DX;
        g_Xa[idx] = (i == j) ? 1.f : 0.f;
    }
}

__global__ void trace_kernel(const float* __restrict__ M, double w) {
    __shared__ float red[256];
    int tid = threadIdx.x;
    float s = 0.f;
    for (int i = tid; i < DK; i += 256) s += M[(size_t)i*DK + i];
    red[tid] = s; __syncthreads();
    for (int o = 128; o > 0; o >>= 1) {
        if (tid < o) red[tid] += red[tid+o];
        __syncthreads();
    }
    if (tid == 0) {
        float t = red[0];
        g_scale = 1.f / (t * t);
        g_logacc += w * log((double)t);
    }
}

__global__ void finalize_kernel() {
    double L = g_logacc;               // log(sigma^2)
    float sigma = (float)exp(0.5 * L);
    if (sigma < 1e-5f) sigma = 1e-5f;
    g_kscale = 1.f / (sigma + 0.002f);
}

__global__ void pack_kernel() {
    int idx = blockIdx.x * blockDim.x + threadIdx.x;   // DX*DX
    int n = idx >> 9, h = idx & 511;
    // Apack[h4][n][j] = A[n][4*h4+j]
    g_Apack[(h >> 2) * (DX*4) + n*4 + (h & 3)] = g_Amat[(size_t)n*DX + h];
}

__global__ void dcopy_kernel(const float* __restrict__ Kraw) {
    int idx = blockIdx.x * blockDim.x + threadIdx.x;   // DOUT*DU
    int o = idx >> 8, h = idx & 255;
    g_E[(size_t)o*DK + DX + h] = g_kscale * Kraw[(size_t)(DX+o)*DK + DX + h]; // GAMMA=1
}

__global__ void state0_kernel(const float* __restrict__ st, float* __restrict__ states) {
    int idx = blockIdx.x * blockDim.x + threadIdx.x;   // NB*DX
    int b = idx >> 9, n = idx & 511;
    states[(size_t)b*(SEQL+1)*DX + n] = st[idx];
}

// ---------------- generic tiled SGEMM:  C = alpha*op(A)op(B) + beta*Dm ----------------
// BM=BN=64, BK=16, 256 threads, 4x4 microtile. All used shapes divide the tiles.
template<bool TA, bool TB>
__global__ __launch_bounds__(256)
void sgemm_kernel(const float* __restrict__ A, const float* __restrict__ B,
                  const float* __restrict__ Dm, float* __restrict__ C,
                  int M, int N, int K, int lda, int ldb, int ldd, int ldc,
                  int amode, float alpha_c, float beta,
                  int rpb, long long bstr)
{
    __shared__ float As[16][68];
    __shared__ float Bs[16][68];
    int tid = threadIdx.x;
    int tx = tid & 15, ty = tid >> 4;
    int m0 = blockIdx.y * 64, n0 = blockIdx.x * 64;
    float acc[4][4] = {};

    for (int kt = 0; kt < K; kt += 16) {
        #pragma unroll
        for (int i = 0; i < 4; ++i) {
            int idx = tid + i*256;
            if (TA) {
                int k = idx >> 6, m = idx & 63;
                As[k][m] = A[(size_t)(kt+k)*lda + (m0+m)];
            } else {
                int m = idx >> 4, k = idx & 15;
                int gm = m0 + m;
                const float* arow;
                if (rpb > 0) { int bb = gm / rpb; int r = gm - bb*rpb;
                               arow = A + (size_t)bb*bstr + (size_t)r*lda; }
                else           arow = A + (size_t)gm*lda;
                As[k][m] = arow[kt + k];
            }
            if (TB) {
                int n = idx >> 4, k = idx & 15;
                Bs[k][n] = B[(size_t)(n0+n)*ldb + (kt+k)];
            } else {
                int k = idx >> 6, n = idx & 63;
                Bs[k][n] = B[(size_t)(kt+k)*ldb + (n0+n)];
            }
        }
        __syncthreads();
        #pragma unroll
        for (int kk = 0; kk < 16; ++kk) {
            float4 av = *(float4*)&As[kk][ty*4];
            float4 bv = *(float4*)&Bs[kk][tx*4];
            float a[4] = {av.x, av.y, av.z, av.w};
            float b[4] = {bv.x, bv.y, bv.z, bv.w};
            #pragma unroll
            for (int i = 0; i < 4; ++i)
                #pragma unroll
                for (int j = 0; j < 4; ++j)
                    acc[i][j] += a[i]*b[j];
        }
        __syncthreads();
    }

    float alpha = alpha_c;
    if (amode == 1) alpha *= g_scale;
    else if (amode == 2) alpha *= g_kscale;

    #pragma unroll
    for (int i = 0; i < 4; ++i) {
        int gm = m0 + ty*4 + i;
        float4 v;
        v.x = alpha*acc[i][0]; v.y = alpha*acc[i][1];
        v.z = alpha*acc[i][2]; v.w = alpha*acc[i][3];
        if (beta != 0.f) {
            float4 d = *(const float4*)&Dm[(size_t)gm*ldd + n0 + tx*4];
            v.x += beta*d.x; v.y += beta*d.y; v.z += beta*d.z; v.w += beta*d.w;
        }
        *(float4*)&C[(size_t)gm*ldc + n0 + tx*4] = v;
    }
}

// ---------------- scan: chunked recurrence with warmup ----------------
// grid = 128 (64 chunks x 2 batch-halves), block = 512 threads (one per state col)
__global__ __launch_bounds__(512)
void scan_kernel(const float* __restrict__ Bu, const float* __restrict__ Apack,
                 const float* __restrict__ state0, float* __restrict__ states)
{
    __shared__ float xs[8][DX];
    int n = threadIdx.x;
    int c = blockIdx.x >> 1, half = blockIdx.x & 1, b0 = half * 8;
    int t0 = c * CT;
    int tstart = (c == 0) ? 0 : (t0 - CW);

    #pragma unroll
    for (int b = 0; b < 8; ++b)
        xs[b][n] = (c == 0) ? state0[(size_t)(b0+b)*DX + n] : 0.f;
    __syncthreads();

    for (int t = tstart; t < t0 + CT; ++t) {
        float acc[8];
        #pragma unroll
        for (int b = 0; b < 8; ++b)
            acc[b] = Bu[((size_t)(b0+b)*SEQL + t)*DX + n];
        #pragma unroll 2
        for (int h4 = 0; h4 < DX/4; ++h4) {
            float4 a = *(const float4*)(Apack + (size_t)h4*(DX*4) + n*4);
            #pragma unroll
            for (int b = 0; b < 8; ++b) {
                float4 xv = *(const float4*)(&xs[b][h4*4]);
                acc[b] += a.x*xv.x + a.y*xv.y + a.z*xv.z + a.w*xv.w;
            }
        }
        __syncthreads();
        bool wr = (t >= t0);
        #pragma unroll
        for (int b = 0; b < 8; ++b) {
            xs[b][n] = acc[b];
            if (wr)
                states[((size_t)(b0+b)*(SEQL+1) + (t+1))*DX + n] = acc[b];
        }
        __syncthreads();
    }
}

// ---------------- host ----------------
static void* symaddr(const void* sym) {
    void* p = nullptr;
    cudaGetSymbolAddress(&p, sym);
    return p;
}

static void GEMM(bool TA, bool TB, const float* A, const float* B, const float* Dm, float* C,
                 int M, int N, int K, int lda, int ldb, int ldd, int ldc,
                 int amode, float ac, float beta, int rpb, long long bstr)
{
    dim3 g(N/64, M/64), blk(256);
    if (TA) {
        if (TB) sgemm_kernel<true,true ><<<g,blk>>>(A,B,Dm,C,M,N,K,lda,ldb,ldd,ldc,amode,ac,beta,rpb,bstr);
        else    sgemm_kernel<true,false><<<g,blk>>>(A,B,Dm,C,M,N,K,lda,ldb,ldd,ldc,amode,ac,beta,rpb,bstr);
    } else {
        if (TB) sgemm_kernel<false,true ><<<g,blk>>>(A,B,Dm,C,M,N,K,lda,ldb,ldd,ldc,amode,ac,beta,rpb,bstr);
        else    sgemm_kernel<false,false><<<g,blk>>>(A,B,Dm,C,M,N,K,lda,ldb,ldd,ldc,amode,ac,beta,rpb,bstr);
    }
}

extern "C" void kernel_launch(void* const* d_in, const int* in_sizes, int n_in,
                              void* d_out, int out_size)
{
    const float *u = nullptr, *state = nullptr, *S = nullptr, *Kraw = nullptr;
    for (int i = 0; i < n_in; ++i) {
        long long sz = in_sizes[i];
        if      (sz == (long long)NB*SEQL*DU) u     = (const float*)d_in[i];
        else if (sz == (long long)NB*DX)      state = (const float*)d_in[i];
        else if (sz == (long long)DX*DX)      S     = (const float*)d_in[i];
        else if (sz == (long long)DK*DK)      Kraw  = (const float*)d_in[i];
    }
    float* out = (float*)d_out;

    float* pM0    = (float*)symaddr(g_M0);
    float* pM1    = (float*)symaddr(g_M1);
    float* pXa    = (float*)symaddr(g_Xa);
    float* pXb    = (float*)symaddr(g_Xb);
    float* pP     = (float*)symaddr(g_P);
    float* pT1    = (float*)symaddr(g_T1);
    float* pAmat  = (float*)symaddr(g_Amat);
    float* pApack = (float*)symaddr(g_Apack);
    float* pBm    = (float*)symaddr(g_Bm);
    float* pE     = (float*)symaddr(g_E);
    float* pBu    = (float*)symaddr(g_Bu);
    float* pFall  = (float*)symaddr(g_states_fallback);

    float* states = ((long long)out_size >= (long long)OUT_ELEMS + (long long)ST_ELEMS)
                    ? (out + OUT_ELEMS) : pFall;

    // --- init (logacc=0, X0=I) ---
    init_kernel<<<(DX*DX + 255)/256, 256>>>();

    // --- sigma: M0 = K^T K, then 10 trace-normalized squarings ---
    GEMM(true, false, Kraw, Kraw, nullptr, pM0, DK, DK, DK, DK, DK, 0, DK, 0, 1.f, 0.f, 0, 0);
    float* Ms[2] = {pM0, pM1};
    double w = 1.0;
    for (int i = 0; i < 10; ++i) {
        trace_kernel<<<1,256>>>(Ms[i & 1], w);
        w *= 0.5;
        GEMM(false, false, Ms[i & 1], Ms[i & 1], nullptr, Ms[(i+1) & 1],
             DK, DK, DK, DK, DK, 0, DK, 1, 1.f, 0.f, 0, 0);
    }
    trace_kernel<<<1,256>>>(Ms[0], w);   // M10 lives in buffer 0; w = 1/1024
    finalize_kernel<<<1,1>>>();

    // --- Sinv via Newton-Schulz: X <- X(2I - S X), 7 iters ---
    float* Xc = pXa; float* Xn = pXb;
    for (int it = 0; it < 7; ++it) {
        GEMM(false, false, S,  Xc, nullptr, pP, DX, DX, DX, DX, DX, 0,  DX, 0,  1.f, 0.f, 0, 0);
        GEMM(false, false, Xc, pP, Xc,      Xn, DX, DX, DX, DX, DX, DX, DX, 0, -1.f, 2.f, 0, 0);
        float* tmp = Xc; Xc = Xn; Xn = tmp;
    }
    // Xc == Sinv

    // --- assemble A, B, C, D (all carry kscale; GAMMA=1) ---
    GEMM(false, false, Kraw, S,   nullptr, pT1,   DX, DX, DX, DK, DX, 0, DX, 2, 1.f, 0.f, 0, 0); // T1 = ks*K11@S
    GEMM(false, false, Xc,   pT1, nullptr, pAmat, DX, DX, DX, DX, DX, 0, DX, 0, 1.f, 0.f, 0, 0); // A = Sinv@T1
    pack_kernel<<<(DX*DX)/256, 256>>>();
    GEMM(false, false, Xc, Kraw + DX, nullptr, pBm, DX, DU, DX, DX, DK, 0, DU, 2, 1.f, 0.f, 0, 0); // B = ks*Sinv@K12
    GEMM(false, false, Kraw + (size_t)DX*DK, S, nullptr, pE, DOUT, DX, DX, DK, DX, 0, DK, 2, 1.f, 0.f, 0, 0); // C = ks*K21@S
    dcopy_kernel<<<(DOUT*DU)/256, 256>>>(Kraw);  // D block of E

    // --- Bu = u @ B^T  [65536 x 512] ---
    GEMM(false, true, u, pBm, nullptr, pBu, NB*SEQL, DX, DU, DU, DU, 0, DX, 0, 1.f, 0.f, 0, 0);

    // --- scan (writes states rows 1..4096; row 0 from state input) ---
    state0_kernel<<<(NB*DX)/256, 256>>>(state, states);
    scan_kernel<<<128, 512>>>(pBu, pApack, state, states);

    // --- output = pre_states @ C^T + u @ D^T ---
    GEMM(false, true, states, pE, nullptr, out, NB*SEQL, DOUT, DX, DX, DK, 0, DOUT,
         0, 1.f, 0.f, SEQL, (long long)(SEQL+1)*DX);
    GEMM(false, true, u, pE + DX, out, out, NB*SEQL, DOUT, DU, DU, DK, DOUT, DOUT,
         0, 1.f, 1.f, 0, 0);
}